// round 14
// baseline (speedup 1.0000x reference)
#include <cuda_runtime.h>
#include <cuda_fp16.h>
#include <cstdint>

#define N_B 4096
#define NTHREADS 512

// ---------------- smem layout (bytes) ----------------
#define SM_B     0        // 32768  W2 [n][k] fp16, swizzled (read once into regs)
#define SM_A     32768    // 16384  A  [m=64][k] fp16, swizzled
#define SM_W1    49152    // 4096   W1 [k][col] f32
#define SM_EPI   53248    // 2048   per-col float4 {b2, w3_0, w3_1, 0}
#define SM_B1    55296    // 512
#define SM_FEAT  55808    // 2048   feat[64][8] f32
#define SM_PART  57856    // 4096   partial[2 buf][4 cq][64 rows] float2
#define SM_B3    61952    // 8
#define SMEM_TOTAL 62016

// ---------------- helpers ----------------
__device__ __forceinline__ uint32_t smem_u32_of(const void* p) {
    uint32_t a;
    asm("{ .reg .u64 t; cvta.to.shared.u64 t, %1; cvt.u32.u64 %0, t; }" : "=r"(a) : "l"(p));
    return a;
}
__device__ __forceinline__ unsigned long long pack_dup(float v) {
    unsigned long long r; asm("mov.b64 %0, {%1, %1};" : "=l"(r) : "f"(v)); return r;
}
__device__ __forceinline__ unsigned long long ffma2(unsigned long long a, unsigned long long b,
                                                    unsigned long long c) {
    unsigned long long d; asm("fma.rn.f32x2 %0, %1, %2, %3;" : "=l"(d) : "l"(a), "l"(b), "l"(c));
    return d;
}
__device__ __forceinline__ float2 unpack2(unsigned long long v) {
    float2 r; asm("mov.b64 {%0, %1}, %2;" : "=f"(r.x), "=f"(r.y) : "l"(v)); return r;
}
__device__ __forceinline__ uint32_t cvt2hf(float hi, float lo) {  // hi->upper16, lo->lower16
    uint32_t r; asm("cvt.rn.f16x2.f32 %0, %1, %2;" : "=r"(r) : "f"(hi), "f"(lo)); return r;
}
__device__ __forceinline__ void ldsm4(uint32_t* r, uint32_t addr) {
    asm volatile("ldmatrix.sync.aligned.m8n8.x4.shared.b16 {%0,%1,%2,%3}, [%4];"
                 : "=r"(r[0]), "=r"(r[1]), "=r"(r[2]), "=r"(r[3]) : "r"(addr));
}
__device__ __forceinline__ void mma16816(float* d, const uint32_t* a, uint32_t b0, uint32_t b1) {
    asm volatile("mma.sync.aligned.m16n8k16.row.col.f32.f16.f16.f32 "
                 "{%0,%1,%2,%3}, {%4,%5,%6,%7}, {%8,%9}, {%0,%1,%2,%3};"
                 : "+f"(d[0]), "+f"(d[1]), "+f"(d[2]), "+f"(d[3])
                 : "r"(a[0]), "r"(a[1]), "r"(a[2]), "r"(a[3]), "r"(b0), "r"(b1));
}
__device__ __forceinline__ void barx(int id) {
    asm volatile("bar.sync %0, 128;" :: "r"(id) : "memory");
}

// per-warp conv: features + L1 + fp16 convert for 4 rows starting at local row r0.
template <int DIR>
__device__ __forceinline__ void conv_warp(char* sm, const float* __restrict__ x,
                                          const float* __restrict__ t, int b, int i0,
                                          int r0, int lane)
{
    float* sFeat = (float*)(sm + SM_FEAT);
    if (lane < 4) {
        const int m = r0 + lane, i = i0 + m;
        const float* xb = x + (size_t)b * 514;
        const float2 xi  = *(const float2*)(xb + i * 2);
        const float2 xi1 = *(const float2*)(xb + i * 2 + 2);
        const float2 pt  = *(const float2*)(xb + 512);
        const float tb = t[b];
        float* f = sFeat + m * 8;
        if (DIR == 0) { f[0]=xi1.x; f[1]=xi1.y; f[2]=tb; f[3]=xi.x;  f[4]=xi.y;  f[5]=(float)(i+1)*(1.f/256.f); }
        else          { f[0]=xi.x;  f[1]=xi.y;  f[2]=tb; f[3]=xi1.x; f[4]=xi1.y; f[5]=(float)i*(1.f/256.f); }
        f[6]=pt.x; f[7]=pt.y;
    }
    __syncwarp();

    const float* sW1 = (const float*)(sm + SM_W1);
    unsigned long long w1p[16];
    #pragma unroll
    for (int k = 0; k < 8; k++) {
        const ulonglong2 q = *(const ulonglong2*)(sW1 + k * 128 + lane * 4);
        w1p[2 * k] = q.x; w1p[2 * k + 1] = q.y;
    }
    const ulonglong2 b1q = *(const ulonglong2*)((const float*)(sm + SM_B1) + lane * 4);

    char* sa = sm + SM_A;
    const uint32_t chk = lane >> 1;
    const uint32_t halfsel = (lane & 1) * 8;
    #pragma unroll
    for (int j = 0; j < 4; j++) {
        const int m = r0 + j;
        const float* f = sFeat + m * 8;
        const float4 fa = *(const float4*)(f);
        const float4 fb = *(const float4*)(f + 4);
        unsigned long long a0 = b1q.x, a1 = b1q.y;
        a0 = ffma2(pack_dup(fa.x), w1p[0],  a0); a1 = ffma2(pack_dup(fa.x), w1p[1],  a1);
        a0 = ffma2(pack_dup(fa.y), w1p[2],  a0); a1 = ffma2(pack_dup(fa.y), w1p[3],  a1);
        a0 = ffma2(pack_dup(fa.z), w1p[4],  a0); a1 = ffma2(pack_dup(fa.z), w1p[5],  a1);
        a0 = ffma2(pack_dup(fa.w), w1p[6],  a0); a1 = ffma2(pack_dup(fa.w), w1p[7],  a1);
        a0 = ffma2(pack_dup(fb.x), w1p[8],  a0); a1 = ffma2(pack_dup(fb.x), w1p[9],  a1);
        a0 = ffma2(pack_dup(fb.y), w1p[10], a0); a1 = ffma2(pack_dup(fb.y), w1p[11], a1);
        a0 = ffma2(pack_dup(fb.z), w1p[12], a0); a1 = ffma2(pack_dup(fb.z), w1p[13], a1);
        a0 = ffma2(pack_dup(fb.w), w1p[14], a0); a1 = ffma2(pack_dup(fb.w), w1p[15], a1);
        const float2 v01 = unpack2(a0), v23 = unpack2(a1);
        const float v0 = fmaxf(v01.x, 0.f), v1 = fmaxf(v01.y, 0.f);
        const float v2 = fmaxf(v23.x, 0.f), v3 = fmaxf(v23.y, 0.f);
        const uint32_t h0 = cvt2hf(v1, v0), h1 = cvt2hf(v3, v2);
        const uint32_t off = (uint32_t)m * 256 + (((chk ^ (uint32_t)(m & 7)) << 4)) + halfsel;
        *(uint2*)(sa + off) = make_uint2(h0, h1);
    }
    __syncwarp();
}

template <int DIR>
__global__ void __launch_bounds__(NTHREADS, 1)
fused_kernel(const float* __restrict__ x, const float* __restrict__ t,
             const float* __restrict__ W1, const float* __restrict__ b1v,
             const float* __restrict__ W2, const float* __restrict__ b2v,
             const float* __restrict__ W3, const float* __restrict__ b3v,
             float* __restrict__ out, int ntiles)
{
    extern __shared__ __align__(1024) char sm[];
    const int tid = threadIdx.x, wid = tid >> 5, lane = tid & 31;
    const int rw = wid >> 2;          // row-group 0..3 (16 rows each -> 64-row tile)
    const int cq = wid & 3;           // column quarter 0..3 (32 cols)
    const uint32_t smb = smem_u32_of(sm);

    // ---- prologue: transpose W2 into [n][k] fp16, small weights ----
    for (int idx = tid; idx < 16384; idx += NTHREADS) {
        const int n = idx >> 7, k = idx & 127;
        const float w = W2[k * 128 + n];
        const uint32_t off = (uint32_t)n * 256 + ((((uint32_t)(k >> 3) ^ (uint32_t)(n & 7)) << 4)) +
                             (uint32_t)(k & 7) * 2;
        *(__half*)(sm + SM_B + off) = __float2half_rn(w);
    }
    float* sW1 = (float*)(sm + SM_W1);
    for (int idx = tid; idx < 1024; idx += NTHREADS) sW1[idx] = W1[idx];
    if (tid < 128) {
        float4 e; e.x = b2v[tid]; e.y = W3[tid * 2]; e.z = W3[tid * 2 + 1]; e.w = 0.f;
        ((float4*)(sm + SM_EPI))[tid] = e;
        ((float*)(sm + SM_B1))[tid] = b1v[tid];
    }
    if (tid == 0) ((float2*)(sm + SM_B3))[0] = make_float2(b3v[0], b3v[1]);
    __syncthreads();

    const float2 b3 = ((const float2*)(sm + SM_B3))[0];

    // ---- load this warp's B column-quarter into registers, ONCE ----
    // nB rows for this quarter; ldsm group g covers n-cols [cq*32+g*16, +16)
    uint32_t breg[8][2][4];
    {
        const uint32_t nBq = (uint32_t)(cq * 32) + (uint32_t)(lane & 7) + (uint32_t)((lane & 16) >> 1);
        const uint32_t rowB_off = nBq * 256;
        const uint32_t rxB = nBq & 7;
        const uint32_t cB_bit = (uint32_t)((lane >> 3) & 1);
        #pragma unroll
        for (int kb = 0; kb < 8; kb++) {
            const uint32_t cB = (uint32_t)(2 * kb) + cB_bit;
            const uint32_t o = rowB_off + ((cB ^ rxB) << 4);
            ldsm4(breg[kb][0], smb + SM_B + o);
            ldsm4(breg[kb][1], smb + SM_B + o + 4096);
        }
    }

    // ldmatrix lane-address components for A
    const uint32_t rA = (uint32_t)(rw * 16) + (uint32_t)(lane & 15);
    const uint32_t rowA_off = rA * 256;
    const uint32_t rxA = rA & 7;
    const uint32_t cA_bit = (uint32_t)(lane >> 4);
    const uint32_t aA = smb + SM_A;
    const float4* epi = (const float4*)(sm + SM_EPI);
    const int barid = 1 + rw;         // named barrier per row-group (ids 1..4)

    // Row-group-consistent stagger.
    const int K = (ntiles + gridDim.x - 1) / (int)gridDim.x;
    const int off0 = (rw * K) >> 2;

    for (int k = 0; k < K; k++) {
        int kk = k + off0; if (kk >= K) kk -= K;
        const int tt = (int)blockIdx.x + kk * (int)gridDim.x;
        if (tt >= ntiles) continue;
        const int b = tt >> 2;            // four 64-row tiles per batch
        const int i0 = (tt & 3) << 6;

        // conv: this warp converts 4 rows (group covers its 16-row block)
        conv_warp<DIR>(sm, x, t, b, i0, rw * 16 + cq * 4, lane);
        barx(barid);                      // group's A rows ready

        float acc[4][4];
        #pragma unroll
        for (int nb = 0; nb < 4; nb++)
            { acc[nb][0] = 0.f; acc[nb][1] = 0.f; acc[nb][2] = 0.f; acc[nb][3] = 0.f; }

        #pragma unroll
        for (int kb = 0; kb < 8; kb++) {
            const uint32_t cA = (uint32_t)(2 * kb) + cA_bit;
            uint32_t a[4];
            ldsm4(a, aA + rowA_off + ((cA ^ rxA) << 4));
            mma16816(acc[0], a, breg[kb][0][0], breg[kb][0][1]);
            mma16816(acc[1], a, breg[kb][0][2], breg[kb][0][3]);
            mma16816(acc[2], a, breg[kb][1][0], breg[kb][1][1]);
            mma16816(acc[3], a, breg[kb][1][2], breg[kb][1][3]);
        }

        // ---- epilogue: relu(acc + b2) @ W3 over this col quarter, 4-lane reduce ----
        float pa0 = 0.f, pa1 = 0.f, pb0 = 0.f, pb1 = 0.f;
        #pragma unroll
        for (int nb = 0; nb < 4; nb++) {
            const int col0 = cq * 32 + nb * 8 + 2 * (lane & 3);
            const float4 e0 = epi[col0], e1 = epi[col0 + 1];
            float v;
            v = fmaxf(acc[nb][0] + e0.x, 0.f); pa0 += v * e0.y; pa1 += v * e0.z;
            v = fmaxf(acc[nb][1] + e1.x, 0.f); pa0 += v * e1.y; pa1 += v * e1.z;
            v = fmaxf(acc[nb][2] + e0.x, 0.f); pb0 += v * e0.y; pb1 += v * e0.z;
            v = fmaxf(acc[nb][3] + e1.x, 0.f); pb0 += v * e1.y; pb1 += v * e1.z;
        }
        #pragma unroll
        for (int s = 1; s <= 2; s <<= 1) {
            pa0 += __shfl_xor_sync(0xffffffffu, pa0, s);
            pa1 += __shfl_xor_sync(0xffffffffu, pa1, s);
            pb0 += __shfl_xor_sync(0xffffffffu, pb0, s);
            pb1 += __shfl_xor_sync(0xffffffffu, pb1, s);
        }

        float2* sPart = (float2*)(sm + SM_PART + (k & 1) * 2048) + cq * 64;
        const int q = lane >> 2;
        const int m1 = rw * 16 + q;       // local rows m1 and m1+8
        if (cq != 0 && (lane & 3) == 0) {
            sPart[m1]     = make_float2(pa0, pa1);
            sPart[m1 + 8] = make_float2(pb0, pb1);
        }
        barx(barid);                      // partials visible; group's MMA done -> A reusable
        if (cq == 0 && (lane & 3) == 0) {
            const float2* sp = (const float2*)(sm + SM_PART + (k & 1) * 2048);
            float r10 = pa0 + b3.x, r11 = pa1 + b3.y;
            float r20 = pb0 + b3.x, r21 = pb1 + b3.y;
            #pragma unroll
            for (int c = 1; c < 4; c++) {
                const float2 q1 = sp[c * 64 + m1], q2 = sp[c * 64 + m1 + 8];
                r10 += q1.x; r11 += q1.y; r20 += q2.x; r21 += q2.y;
            }
            float* ob = out + (size_t)b * 512;
            const int i1 = i0 + m1, i2 = i1 + 8;
            if (DIR == 0) {
                if (i1 == 0) *(float2*)ob = make_float2(0.f, 0.f);
                if (i1 < 255) *(float2*)(ob + (i1 + 1) * 2) = make_float2(r10, r11);
                if (i2 < 255) *(float2*)(ob + (i2 + 1) * 2) = make_float2(r20, r21);
            } else {
                if (i1 < 255) {
                    float2* o = (float2*)(ob + i1 * 2);
                    const float2 v = *o; *o = make_float2(v.x + r10, v.y + r11);
                }
                if (i2 < 255) {
                    float2* o = (float2*)(ob + i2 * 2);
                    const float2 v = *o; *o = make_float2(v.x + r20, v.y + r21);
                }
            }
        }
        __syncwarp();
    }
}

// ---------------- init MLP (3->128->128->2, 4096 rows) ----------------
__global__ void __launch_bounds__(128)
init_kernel(const float* __restrict__ x, const float* __restrict__ t,
            const float* __restrict__ W1, const float* __restrict__ b1,
            const float* __restrict__ W2, const float* __restrict__ b2,
            const float* __restrict__ W3, const float* __restrict__ b3,
            float* __restrict__ out, int nrows)
{
    extern __shared__ float ism[];
    float* sW2 = ism;           // 16384
    float* sh  = ism + 16384;   // 128
    float* red = ism + 16512;   // 8
    const int tid = threadIdx.x;
    for (int i = tid; i < 16384; i += 128) sW2[i] = W2[i];
    const float w10 = W1[tid], w11 = W1[128 + tid], w12 = W1[256 + tid];
    const float bb1 = b1[tid], bb2 = b2[tid];
    const float w30 = W3[tid * 2], w31 = W3[tid * 2 + 1];
    __syncthreads();
    for (int r = blockIdx.x; r < nrows; r += gridDim.x) {
        const float2 x0 = *(const float2*)(x + (size_t)r * 514);
        const float tb = t[r];
        sh[tid] = fmaxf(bb1 + x0.x * w10 + x0.y * w11 + tb * w12, 0.f);
        __syncthreads();
        float a = bb2;
        #pragma unroll 8
        for (int k = 0; k < 128; k++) a += sh[k] * sW2[k * 128 + tid];
        a = fmaxf(a, 0.f);
        float p0 = a * w30, p1 = a * w31;
        #pragma unroll
        for (int s = 16; s; s >>= 1) {
            p0 += __shfl_xor_sync(0xffffffffu, p0, s);
            p1 += __shfl_xor_sync(0xffffffffu, p1, s);
        }
        if ((tid & 31) == 0) { red[tid >> 5] = p0; red[4 + (tid >> 5)] = p1; }
        __syncthreads();
        if (tid == 0) {
            const float q0 = red[0] + red[1] + red[2] + red[3] + b3[0];
            const float q1 = red[4] + red[5] + red[6] + red[7] + b3[1];
            float2* o = (float2*)(out + (size_t)r * 512);
            const float2 v = *o; *o = make_float2(v.x + q0, v.y + q1);
        }
        __syncthreads();
    }
}

extern "C" void kernel_launch(void* const* d_in, const int* in_sizes, int n_in,
                              void* d_out, int out_size)
{
    (void)in_sizes; (void)n_in; (void)out_size;
    const float* x = (const float*)d_in[0];
    const float* t = (const float*)d_in[1];
    float* out = (float*)d_out;

    static int grid = 0;
    if (grid == 0) {
        int dev = 0, sms = 148;
        cudaGetDevice(&dev);
        cudaDeviceGetAttribute(&sms, cudaDevAttrMultiProcessorCount, dev);
        grid = sms;
        cudaFuncSetAttribute(fused_kernel<0>, cudaFuncAttributeMaxDynamicSharedMemorySize, SMEM_TOTAL);
        cudaFuncSetAttribute(fused_kernel<1>, cudaFuncAttributeMaxDynamicSharedMemorySize, SMEM_TOTAL);
        cudaFuncSetAttribute(init_kernel, cudaFuncAttributeMaxDynamicSharedMemorySize, 16520 * 4);
    }

    const int ntiles = N_B * 4;   // four 64-row tiles per batch

    fused_kernel<0><<<grid, NTHREADS, SMEM_TOTAL>>>(x, t,
        (const float*)d_in[2], (const float*)d_in[3], (const float*)d_in[4],
        (const float*)d_in[5], (const float*)d_in[6], (const float*)d_in[7], out, ntiles);
    fused_kernel<1><<<grid, NTHREADS, SMEM_TOTAL>>>(x, t,
        (const float*)d_in[8], (const float*)d_in[9], (const float*)d_in[10],
        (const float*)d_in[11], (const float*)d_in[12], (const float*)d_in[13], out, ntiles);
    init_kernel<<<304, 128, 16520 * 4>>>(x, t,
        (const float*)d_in[14], (const float*)d_in[15], (const float*)d_in[16],
        (const float*)d_in[17], (const float*)d_in[18], (const float*)d_in[19], out, N_B);
}

// round 15
// speedup vs baseline: 1.4630x; 1.4630x over previous
#include <cuda_runtime.h>
#include <cuda_fp16.h>
#include <cstdint>

#define N_B 4096
#define NTHREADS 512

// ---------------- smem layout (bytes) ----------------
#define SM_B     0        // 32768  W2 [n][k] fp16, swizzled
#define SM_A     32768    // 65536  A/H [m=256][k] fp16, swizzled
#define SM_W1H   98304    // 4096   W1+bias fp16 tile [n=128][k=16] (k8=b1, k9-15=0)
#define SM_EPI   102400   // 2048   per-col float4 {b2, w3_0, w3_1, 0}
#define SM_FEAT  104448   // 8192   feat[256][8] f32
#define SM_B3    112640   // 8
#define SMEM_TOTAL 112704

// ---------------- helpers ----------------
__device__ __forceinline__ uint32_t smem_u32_of(const void* p) {
    uint32_t a;
    asm("{ .reg .u64 t; cvta.to.shared.u64 t, %1; cvt.u32.u64 %0, t; }" : "=r"(a) : "l"(p));
    return a;
}
__device__ __forceinline__ uint32_t cvt2hf(float hi, float lo) {  // hi->upper16, lo->lower16
    uint32_t r; asm("cvt.rn.f16x2.f32 %0, %1, %2;" : "=r"(r) : "f"(hi), "f"(lo)); return r;
}
__device__ __forceinline__ void ldsm4(uint32_t* r, uint32_t addr) {
    asm volatile("ldmatrix.sync.aligned.m8n8.x4.shared.b16 {%0,%1,%2,%3}, [%4];"
                 : "=r"(r[0]), "=r"(r[1]), "=r"(r[2]), "=r"(r[3]) : "r"(addr));
}
__device__ __forceinline__ void stsm4(uint32_t addr, uint32_t r0, uint32_t r1,
                                      uint32_t r2, uint32_t r3) {
    asm volatile("stmatrix.sync.aligned.m8n8.x4.shared.b16 [%0], {%1,%2,%3,%4};"
                 :: "r"(addr), "r"(r0), "r"(r1), "r"(r2), "r"(r3) : "memory");
}
__device__ __forceinline__ void mma16816(float* d, const uint32_t* a, uint32_t b0, uint32_t b1) {
    asm volatile("mma.sync.aligned.m16n8k16.row.col.f32.f16.f16.f32 "
                 "{%0,%1,%2,%3}, {%4,%5,%6,%7}, {%8,%9}, {%0,%1,%2,%3};"
                 : "+f"(d[0]), "+f"(d[1]), "+f"(d[2]), "+f"(d[3])
                 : "r"(a[0]), "r"(a[1]), "r"(a[2]), "r"(a[3]), "r"(b0), "r"(b1));
}

// per-warp conv via tensor core: feat (K=16, col8=1.0 bias feature) @ W1H -> relu -> stmatrix
template <int DIR>
__device__ __forceinline__ void conv_mma(char* sm, uint32_t smb, const float* __restrict__ x,
                                         const float* __restrict__ t, int b,
                                         int wid, int lane)
{
    float* sFeat = (float*)(sm + SM_FEAT);
    const int r0 = wid * 16;
    if (lane < 16) {
        const int m = r0 + lane, i = m;
        const float* xb = x + (size_t)b * 514;
        const float2 xi  = *(const float2*)(xb + i * 2);
        const float2 xi1 = *(const float2*)(xb + i * 2 + 2);
        const float2 pt  = *(const float2*)(xb + 512);
        const float tb = t[b];
        float* f = sFeat + m * 8;
        if (DIR == 0) { f[0]=xi1.x; f[1]=xi1.y; f[2]=tb; f[3]=xi.x;  f[4]=xi.y;  f[5]=(float)(i+1)*(1.f/256.f); }
        else          { f[0]=xi.x;  f[1]=xi.y;  f[2]=tb; f[3]=xi1.x; f[4]=xi1.y; f[5]=(float)i*(1.f/256.f); }
        f[6]=pt.x; f[7]=pt.y;
    }
    __syncwarp();

    // A fragment (m16k16): rows r0+l/4, r0+l/4+8; k-cols (l&3)*2..+1; k>=8: col8 = 1.0
    const int r = r0 + (lane >> 2);
    const float2 f0 = *(const float2*)(sFeat + r * 8 + 2 * (lane & 3));
    const float2 f1 = *(const float2*)(sFeat + (r + 8) * 8 + 2 * (lane & 3));
    uint32_t a[4];
    a[0] = cvt2hf(f0.y, f0.x);
    a[1] = cvt2hf(f1.y, f1.x);
    a[2] = ((lane & 3) == 0) ? 0x00003C00u : 0u;   // col8 = 1.0 (bias feature)
    a[3] = a[2];

    const uint32_t w1base = smb + SM_W1H +
        ((uint32_t)(lane & 7) + (((uint32_t)lane >> 4) & 1) * 8) * 32 +
        (((uint32_t)lane >> 3) & 1) * 16;
    const uint32_t mRow = (uint32_t)r0 + (((uint32_t)lane >> 3) & 1) * 8 + (uint32_t)(lane & 7);
    const uint32_t stBase = smb + SM_A + mRow * 256;
    const uint32_t chunksel = (uint32_t)lane >> 4;

    #pragma unroll
    for (int p = 0; p < 8; p++) {
        uint32_t w1f[4];
        ldsm4(w1f, w1base + (uint32_t)p * 512);
        float h0[4] = {0.f, 0.f, 0.f, 0.f}, h1[4] = {0.f, 0.f, 0.f, 0.f};
        mma16816(h0, a, w1f[0], w1f[1]);
        mma16816(h1, a, w1f[2], w1f[3]);
        const uint32_t u0 = cvt2hf(fmaxf(h0[1], 0.f), fmaxf(h0[0], 0.f));
        const uint32_t u1 = cvt2hf(fmaxf(h0[3], 0.f), fmaxf(h0[2], 0.f));
        const uint32_t u2 = cvt2hf(fmaxf(h1[1], 0.f), fmaxf(h1[0], 0.f));
        const uint32_t u3 = cvt2hf(fmaxf(h1[3], 0.f), fmaxf(h1[2], 0.f));
        const uint32_t addr = stBase + ((((uint32_t)(2 * p) + chunksel) ^ (mRow & 7u)) << 4);
        stsm4(addr, u0, u1, u2, u3);
    }
    __syncwarp();
}

template <int DIR>
__global__ void __launch_bounds__(NTHREADS, 1)
fused_kernel(const float* __restrict__ x, const float* __restrict__ t,
             const float* __restrict__ W1, const float* __restrict__ b1v,
             const float* __restrict__ W2, const float* __restrict__ b2v,
             const float* __restrict__ W3, const float* __restrict__ b3v,
             float* __restrict__ out, int ntiles)
{
    extern __shared__ __align__(1024) char sm[];
    const int tid = threadIdx.x, wid = tid >> 5, lane = tid & 31;
    const uint32_t smb = smem_u32_of(sm);

    // ---- prologue: transpose W2 into [n][k] fp16; build W1H (W1+bias, K=16) ----
    for (int idx = tid; idx < 16384; idx += NTHREADS) {
        const int n = idx >> 7, k = idx & 127;
        const float w = W2[k * 128 + n];
        const uint32_t off = (uint32_t)n * 256 + ((((uint32_t)(k >> 3) ^ (uint32_t)(n & 7)) << 4)) +
                             (uint32_t)(k & 7) * 2;
        *(__half*)(sm + SM_B + off) = __float2half_rn(w);
    }
    for (int idx = tid; idx < 2048; idx += NTHREADS) {
        const int n = idx >> 4, k = idx & 15;
        const float v = (k < 8) ? W1[k * 128 + n] : ((k == 8) ? b1v[n] : 0.f);
        ((__half*)(sm + SM_W1H))[idx] = __float2half_rn(v);
    }
    if (tid < 128) {
        float4 e; e.x = b2v[tid]; e.y = W3[tid * 2]; e.z = W3[tid * 2 + 1]; e.w = 0.f;
        ((float4*)(sm + SM_EPI))[tid] = e;
    }
    if (tid == 0) ((float2*)(sm + SM_B3))[0] = make_float2(b3v[0], b3v[1]);
    __syncthreads();

    const float2 b3 = ((const float2*)(sm + SM_B3))[0];

    // ldmatrix lane-address components
    const uint32_t rA = (uint32_t)(wid * 16) + (uint32_t)(lane & 15);
    const uint32_t rowA_off = rA * 256;
    const uint32_t rxA = rA & 7;
    const uint32_t cA_bit = (uint32_t)(lane >> 4);
    const uint32_t nB = (uint32_t)(lane & 7) + (uint32_t)((lane & 16) >> 1);
    const uint32_t rowB_off = nB * 256;
    const uint32_t rxB = nB & 7;
    const uint32_t cB_bit = (uint32_t)((lane >> 3) & 1);

    const uint32_t aA = smb + SM_A;
    const uint32_t bB = smb + SM_B;
    const float4* epi = (const float4*)(sm + SM_EPI);

    // Warp-staggered tile order (keeps warps de-phased).
    const int K = (ntiles + gridDim.x - 1) / (int)gridDim.x;
    const int off0 = (wid * K) >> 4;

    for (int k = 0; k < K; k++) {
        int kk = k + off0; if (kk >= K) kk -= K;
        const int tt = (int)blockIdx.x + kk * (int)gridDim.x;
        if (tt >= ntiles) continue;
        const int b = tt;                 // one 256-row tile per batch
        conv_mma<DIR>(sm, smb, x, t, b, wid, lane);

        float acc[16][4];
        #pragma unroll
        for (int nb = 0; nb < 16; nb++)
            { acc[nb][0] = 0.f; acc[nb][1] = 0.f; acc[nb][2] = 0.f; acc[nb][3] = 0.f; }

        #pragma unroll 2
        for (int kb = 0; kb < 8; kb++) {
            const uint32_t cA = (uint32_t)(2 * kb) + cA_bit;
            const uint32_t offA = rowA_off + ((cA ^ rxA) << 4);
            uint32_t a[4];
            ldsm4(a, aA + offA);
            const uint32_t cB = (uint32_t)(2 * kb) + cB_bit;
            const uint32_t offB0 = rowB_off + ((cB ^ rxB) << 4);
            #pragma unroll
            for (int nb2 = 0; nb2 < 8; nb2++) {
                uint32_t bf[4];
                ldsm4(bf, bB + offB0 + (uint32_t)nb2 * 4096);
                mma16816(acc[2 * nb2],     a, bf[0], bf[1]);
                mma16816(acc[2 * nb2 + 1], a, bf[2], bf[3]);
            }
        }

        // ---- epilogue: relu(acc + b2) @ W3, 4-lane reduce, store ----
        float pa0 = 0.f, pa1 = 0.f, pb0 = 0.f, pb1 = 0.f;
        #pragma unroll
        for (int nb = 0; nb < 16; nb++) {
            const int col0 = nb * 8 + 2 * (lane & 3);
            const float4 e0 = epi[col0], e1 = epi[col0 + 1];
            float v;
            v = fmaxf(acc[nb][0] + e0.x, 0.f); pa0 += v * e0.y; pa1 += v * e0.z;
            v = fmaxf(acc[nb][1] + e1.x, 0.f); pa0 += v * e1.y; pa1 += v * e1.z;
            v = fmaxf(acc[nb][2] + e0.x, 0.f); pb0 += v * e0.y; pb1 += v * e0.z;
            v = fmaxf(acc[nb][3] + e1.x, 0.f); pb0 += v * e1.y; pb1 += v * e1.z;
        }
        #pragma unroll
        for (int s = 1; s <= 2; s <<= 1) {
            pa0 += __shfl_xor_sync(0xffffffffu, pa0, s);
            pa1 += __shfl_xor_sync(0xffffffffu, pa1, s);
            pb0 += __shfl_xor_sync(0xffffffffu, pb0, s);
            pb1 += __shfl_xor_sync(0xffffffffu, pb1, s);
        }
        if ((lane & 3) == 0) {
            const int q = lane >> 2;
            const int m1 = wid * 16 + q;      // rows m1 and m1+8
            const int i1 = m1, i2 = m1 + 8;
            float* ob = out + (size_t)b * 512;
            if (DIR == 0) {
                if (m1 == 0) *(float2*)ob = make_float2(0.f, 0.f);
                if (i1 < 255) *(float2*)(ob + (i1 + 1) * 2) = make_float2(pa0 + b3.x, pa1 + b3.y);
                if (i2 < 255) *(float2*)(ob + (i2 + 1) * 2) = make_float2(pb0 + b3.x, pb1 + b3.y);
            } else {
                if (i1 < 255) {
                    float2* o = (float2*)(ob + i1 * 2);
                    const float2 v = *o; *o = make_float2(v.x + pa0 + b3.x, v.y + pa1 + b3.y);
                }
                if (i2 < 255) {
                    float2* o = (float2*)(ob + i2 * 2);
                    const float2 v = *o; *o = make_float2(v.x + pb0 + b3.x, v.y + pb1 + b3.y);
                }
            }
        }
        __syncwarp();
    }
}

// ---------------- init MLP (3->128->128->2, 4096 rows) ----------------
__global__ void __launch_bounds__(128)
init_kernel(const float* __restrict__ x, const float* __restrict__ t,
            const float* __restrict__ W1, const float* __restrict__ b1,
            const float* __restrict__ W2, const float* __restrict__ b2,
            const float* __restrict__ W3, const float* __restrict__ b3,
            float* __restrict__ out, int nrows)
{
    extern __shared__ float ism[];
    float* sW2 = ism;           // 16384
    float* sh  = ism + 16384;   // 128
    float* red = ism + 16512;   // 8
    const int tid = threadIdx.x;
    for (int i = tid; i < 16384; i += 128) sW2[i] = W2[i];
    const float w10 = W1[tid], w11 = W1[128 + tid], w12 = W1[256 + tid];
    const float bb1 = b1[tid], bb2 = b2[tid];
    const float w30 = W3[tid * 2], w31 = W3[tid * 2 + 1];
    __syncthreads();
    for (int r = blockIdx.x; r < nrows; r += gridDim.x) {
        const float2 x0 = *(const float2*)(x + (size_t)r * 514);
        const float tb = t[r];
        sh[tid] = fmaxf(bb1 + x0.x * w10 + x0.y * w11 + tb * w12, 0.f);
        __syncthreads();
        float a = bb2;
        #pragma unroll 8
        for (int k = 0; k < 128; k++) a += sh[k] * sW2[k * 128 + tid];
        a = fmaxf(a, 0.f);
        float p0 = a * w30, p1 = a * w31;
        #pragma unroll
        for (int s = 16; s; s >>= 1) {
            p0 += __shfl_xor_sync(0xffffffffu, p0, s);
            p1 += __shfl_xor_sync(0xffffffffu, p1, s);
        }
        if ((tid & 31) == 0) { red[tid >> 5] = p0; red[4 + (tid >> 5)] = p1; }
        __syncthreads();
        if (tid == 0) {
            const float q0 = red[0] + red[1] + red[2] + red[3] + b3[0];
            const float q1 = red[4] + red[5] + red[6] + red[7] + b3[1];
            float2* o = (float2*)(out + (size_t)r * 512);
            const float2 v = *o; *o = make_float2(v.x + q0, v.y + q1);
        }
        __syncthreads();
    }
}

extern "C" void kernel_launch(void* const* d_in, const int* in_sizes, int n_in,
                              void* d_out, int out_size)
{
    (void)in_sizes; (void)n_in; (void)out_size;
    const float* x = (const float*)d_in[0];
    const float* t = (const float*)d_in[1];
    float* out = (float*)d_out;

    static int grid = 0;
    if (grid == 0) {
        int dev = 0, sms = 148;
        cudaGetDevice(&dev);
        cudaDeviceGetAttribute(&sms, cudaDevAttrMultiProcessorCount, dev);
        grid = sms;
        cudaFuncSetAttribute(fused_kernel<0>, cudaFuncAttributeMaxDynamicSharedMemorySize, SMEM_TOTAL);
        cudaFuncSetAttribute(fused_kernel<1>, cudaFuncAttributeMaxDynamicSharedMemorySize, SMEM_TOTAL);
        cudaFuncSetAttribute(init_kernel, cudaFuncAttributeMaxDynamicSharedMemorySize, 16520 * 4);
    }

    const int ntiles = N_B;       // one 256-row tile per batch

    fused_kernel<0><<<grid, NTHREADS, SMEM_TOTAL>>>(x, t,
        (const float*)d_in[2], (const float*)d_in[3], (const float*)d_in[4],
        (const float*)d_in[5], (const float*)d_in[6], (const float*)d_in[7], out, ntiles);
    fused_kernel<1><<<grid, NTHREADS, SMEM_TOTAL>>>(x, t,
        (const float*)d_in[8], (const float*)d_in[9], (const float*)d_in[10],
        (const float*)d_in[11], (const float*)d_in[12], (const float*)d_in[13], out, ntiles);
    init_kernel<<<304, 128, 16520 * 4>>>(x, t,
        (const float*)d_in[14], (const float*)d_in[15], (const float*)d_in[16],
        (const float*)d_in[17], (const float*)d_in[18], (const float*)d_in[19], out, N_B);
}

// round 16
// speedup vs baseline: 1.7586x; 1.2021x over previous
#include <cuda_runtime.h>
#include <cuda_fp16.h>
#include <cstdint>

#define N_B 4096
#define NTHREADS 512

// ---------------- smem layout (bytes) ----------------
#define SM_B     0        // 32768  W2 [n][k] fp16, swizzled
#define SM_A     32768    // 65536  A/H: 2 tiles x [m=128][k] fp16, swizzled
#define SM_W1H   98304    // 4096   W1+bias fp16 tile [n=128][k=16] (k8=b1, k9-15=0)
#define SM_EPI   102400   // 2048   per-col float4 {b2, w3_0, w3_1, 0}
#define SM_FEAT  104448   // 8192   feat: 2 tiles x [128][8] f32
#define SM_PART  112640   // 4096   partial[2 buf][2 tile][128] float2
#define SM_B3    116736   // 8
#define SMEM_TOTAL 116800

// ---------------- helpers ----------------
__device__ __forceinline__ uint32_t smem_u32_of(const void* p) {
    uint32_t a;
    asm("{ .reg .u64 t; cvta.to.shared.u64 t, %1; cvt.u32.u64 %0, t; }" : "=r"(a) : "l"(p));
    return a;
}
__device__ __forceinline__ uint32_t cvt2hf(float hi, float lo) {  // hi->upper16, lo->lower16
    uint32_t r; asm("cvt.rn.f16x2.f32 %0, %1, %2;" : "=r"(r) : "f"(hi), "f"(lo)); return r;
}
__device__ __forceinline__ void ldsm4(uint32_t* r, uint32_t addr) {
    asm volatile("ldmatrix.sync.aligned.m8n8.x4.shared.b16 {%0,%1,%2,%3}, [%4];"
                 : "=r"(r[0]), "=r"(r[1]), "=r"(r[2]), "=r"(r[3]) : "r"(addr));
}
__device__ __forceinline__ void stsm4(uint32_t addr, uint32_t r0, uint32_t r1,
                                      uint32_t r2, uint32_t r3) {
    asm volatile("stmatrix.sync.aligned.m8n8.x4.shared.b16 [%0], {%1,%2,%3,%4};"
                 :: "r"(addr), "r"(r0), "r"(r1), "r"(r2), "r"(r3) : "memory");
}
__device__ __forceinline__ void mma16816(float* d, const uint32_t* a, uint32_t b0, uint32_t b1) {
    asm volatile("mma.sync.aligned.m16n8k16.row.col.f32.f16.f16.f32 "
                 "{%0,%1,%2,%3}, {%4,%5,%6,%7}, {%8,%9}, {%0,%1,%2,%3};"
                 : "+f"(d[0]), "+f"(d[1]), "+f"(d[2]), "+f"(d[3])
                 : "r"(a[0]), "r"(a[1]), "r"(a[2]), "r"(a[3]), "r"(b0), "r"(b1));
}
__device__ __forceinline__ void barx(int id) {
    asm volatile("bar.sync %0, 64;" :: "r"(id) : "memory");
}

// per-warp conv via tensor core for 16 rows (local r0..r0+15) of tile tsel.
// feat K=16 (col8 = 1.0 bias feature); H -> relu -> fp16 -> stmatrix into A[tsel].
template <int DIR>
__device__ __forceinline__ void conv_mma(char* sm, uint32_t smb, const float* __restrict__ x,
                                         const float* __restrict__ t, int b, int tsel,
                                         int r0, int lane)
{
    float* sFeat = (float*)(sm + SM_FEAT + tsel * 4096);
    const int i0 = tsel << 7;
    if (lane < 16) {
        const int m = r0 + lane, i = i0 + m;
        const float* xb = x + (size_t)b * 514;
        const float2 xi  = *(const float2*)(xb + i * 2);
        const float2 xi1 = *(const float2*)(xb + i * 2 + 2);
        const float2 pt  = *(const float2*)(xb + 512);
        const float tb = t[b];
        float* f = sFeat + m * 8;
        if (DIR == 0) { f[0]=xi1.x; f[1]=xi1.y; f[2]=tb; f[3]=xi.x;  f[4]=xi.y;  f[5]=(float)(i+1)*(1.f/256.f); }
        else          { f[0]=xi.x;  f[1]=xi.y;  f[2]=tb; f[3]=xi1.x; f[4]=xi1.y; f[5]=(float)i*(1.f/256.f); }
        f[6]=pt.x; f[7]=pt.y;
    }
    __syncwarp();

    // A fragment (m16k16): rows r0+l/4, +8; k-cols (l&3)*2..+1; col8 = 1.0 bias
    const int r = r0 + (lane >> 2);
    const float2 f0 = *(const float2*)(sFeat + r * 8 + 2 * (lane & 3));
    const float2 f1 = *(const float2*)(sFeat + (r + 8) * 8 + 2 * (lane & 3));
    uint32_t a[4];
    a[0] = cvt2hf(f0.y, f0.x);
    a[1] = cvt2hf(f1.y, f1.x);
    a[2] = ((lane & 3) == 0) ? 0x00003C00u : 0u;
    a[3] = a[2];

    const uint32_t w1base = smb + SM_W1H +
        ((uint32_t)(lane & 7) + (((uint32_t)lane >> 4) & 1) * 8) * 32 +
        (((uint32_t)lane >> 3) & 1) * 16;
    const uint32_t mRow = (uint32_t)r0 + (((uint32_t)lane >> 3) & 1) * 8 + (uint32_t)(lane & 7);
    const uint32_t stBase = smb + SM_A + (uint32_t)tsel * 32768 + mRow * 256;
    const uint32_t chunksel = (uint32_t)lane >> 4;

    #pragma unroll
    for (int p = 0; p < 8; p++) {
        uint32_t w1f[4];
        ldsm4(w1f, w1base + (uint32_t)p * 512);
        float h0[4] = {0.f, 0.f, 0.f, 0.f}, h1[4] = {0.f, 0.f, 0.f, 0.f};
        mma16816(h0, a, w1f[0], w1f[1]);
        mma16816(h1, a, w1f[2], w1f[3]);
        const uint32_t u0 = cvt2hf(fmaxf(h0[1], 0.f), fmaxf(h0[0], 0.f));
        const uint32_t u1 = cvt2hf(fmaxf(h0[3], 0.f), fmaxf(h0[2], 0.f));
        const uint32_t u2 = cvt2hf(fmaxf(h1[1], 0.f), fmaxf(h1[0], 0.f));
        const uint32_t u3 = cvt2hf(fmaxf(h1[3], 0.f), fmaxf(h1[2], 0.f));
        const uint32_t addr = stBase + ((((uint32_t)(2 * p) + chunksel) ^ (mRow & 7u)) << 4);
        stsm4(addr, u0, u1, u2, u3);
    }
    __syncwarp();
}

template <int DIR>
__global__ void __launch_bounds__(NTHREADS, 1)
fused_kernel(const float* __restrict__ x, const float* __restrict__ t,
             const float* __restrict__ W1, const float* __restrict__ b1v,
             const float* __restrict__ W2, const float* __restrict__ b2v,
             const float* __restrict__ W3, const float* __restrict__ b3v,
             float* __restrict__ out, int npairs)
{
    extern __shared__ __align__(1024) char sm[];
    const int tid = threadIdx.x, wid = tid >> 5, lane = tid & 31;
    const int rw = wid >> 1;          // 16-row group 0..7 (128-row tiles)
    const int ch = wid & 1;           // column half 0/1 (64 cols)
    const uint32_t smb = smem_u32_of(sm);

    // ---- prologue: transpose W2 into [n][k] fp16; build W1H (W1+bias, K=16) ----
    for (int idx = tid; idx < 16384; idx += NTHREADS) {
        const int n = idx >> 7, k = idx & 127;
        const float w = W2[k * 128 + n];
        const uint32_t off = (uint32_t)n * 256 + ((((uint32_t)(k >> 3) ^ (uint32_t)(n & 7)) << 4)) +
                             (uint32_t)(k & 7) * 2;
        *(__half*)(sm + SM_B + off) = __float2half_rn(w);
    }
    for (int idx = tid; idx < 2048; idx += NTHREADS) {
        const int n = idx >> 4, k = idx & 15;
        const float v = (k < 8) ? W1[k * 128 + n] : ((k == 8) ? b1v[n] : 0.f);
        ((__half*)(sm + SM_W1H))[idx] = __float2half_rn(v);
    }
    if (tid < 128) {
        float4 e; e.x = b2v[tid]; e.y = W3[tid * 2]; e.z = W3[tid * 2 + 1]; e.w = 0.f;
        ((float4*)(sm + SM_EPI))[tid] = e;
    }
    if (tid == 0) ((float2*)(sm + SM_B3))[0] = make_float2(b3v[0], b3v[1]);
    __syncthreads();

    const float2 b3 = ((const float2*)(sm + SM_B3))[0];

    // ldmatrix lane-address components
    const uint32_t rA = (uint32_t)(rw * 16) + (uint32_t)(lane & 15);
    const uint32_t rowA_off = rA * 256;
    const uint32_t rxA = rA & 7;
    const uint32_t cA_bit = (uint32_t)(lane >> 4);
    const uint32_t nB = (uint32_t)(ch * 64) + (uint32_t)(lane & 7) + (uint32_t)((lane & 16) >> 1);
    const uint32_t rowB_off = nB * 256;
    const uint32_t rxB = nB & 7;
    const uint32_t cB_bit = (uint32_t)((lane >> 3) & 1);

    const uint32_t aA = smb + SM_A;
    const uint32_t bB = smb + SM_B;
    const float4* epi = (const float4*)(sm + SM_EPI);
    const int barid = 1 + rw;         // per-pair named barrier (ids 1..8)

    // Pair-consistent stagger (depends on rw only).
    const int K = (npairs + gridDim.x - 1) / (int)gridDim.x;
    const int off0 = (rw * K) >> 3;

    for (int k = 0; k < K; k++) {
        int kk = k + off0; if (kk >= K) kk -= K;
        const int b = (int)blockIdx.x + kk * (int)gridDim.x;   // one batch = tile pair
        if (b >= npairs) continue;

        // conv: warp (rw,ch) converts rows rw*16..+15 of tile ch
        conv_mma<DIR>(sm, smb, x, t, b, ch, rw * 16, lane);
        barx(barid);                      // both tiles' A rows for this pair ready

        float acc0[8][4], acc1[8][4];
        #pragma unroll
        for (int nb = 0; nb < 8; nb++) {
            acc0[nb][0]=0.f; acc0[nb][1]=0.f; acc0[nb][2]=0.f; acc0[nb][3]=0.f;
            acc1[nb][0]=0.f; acc1[nb][1]=0.f; acc1[nb][2]=0.f; acc1[nb][3]=0.f;
        }

        #pragma unroll 2
        for (int kb = 0; kb < 8; kb++) {
            const uint32_t cA = (uint32_t)(2 * kb) + cA_bit;
            const uint32_t offA = rowA_off + ((cA ^ rxA) << 4);
            uint32_t a0[4], a1[4];
            ldsm4(a0, aA + offA);
            ldsm4(a1, aA + 32768 + offA);
            const uint32_t cB = (uint32_t)(2 * kb) + cB_bit;
            const uint32_t offB0 = rowB_off + ((cB ^ rxB) << 4);
            #pragma unroll
            for (int nb2 = 0; nb2 < 4; nb2++) {
                uint32_t bf[4];
                ldsm4(bf, bB + offB0 + (uint32_t)nb2 * 4096);
                mma16816(acc0[2 * nb2],     a0, bf[0], bf[1]);
                mma16816(acc1[2 * nb2],     a1, bf[0], bf[1]);
                mma16816(acc0[2 * nb2 + 1], a0, bf[2], bf[3]);
                mma16816(acc1[2 * nb2 + 1], a1, bf[2], bf[3]);
            }
        }

        // ---- epilogue per tile: relu(acc+b2) @ W3 over col half, reduce, exchange ----
        float p00 = 0.f, p01 = 0.f, p02 = 0.f, p03 = 0.f;   // tile0 rows m1, m1+8
        float p10 = 0.f, p11 = 0.f, p12 = 0.f, p13 = 0.f;   // tile1
        #pragma unroll
        for (int nb = 0; nb < 8; nb++) {
            const int col0 = ch * 64 + nb * 8 + 2 * (lane & 3);
            const float4 e0 = epi[col0], e1 = epi[col0 + 1];
            float v;
            v = fmaxf(acc0[nb][0] + e0.x, 0.f); p00 += v * e0.y; p01 += v * e0.z;
            v = fmaxf(acc0[nb][1] + e1.x, 0.f); p00 += v * e1.y; p01 += v * e1.z;
            v = fmaxf(acc0[nb][2] + e0.x, 0.f); p02 += v * e0.y; p03 += v * e0.z;
            v = fmaxf(acc0[nb][3] + e1.x, 0.f); p02 += v * e1.y; p03 += v * e1.z;
            v = fmaxf(acc1[nb][0] + e0.x, 0.f); p10 += v * e0.y; p11 += v * e0.z;
            v = fmaxf(acc1[nb][1] + e1.x, 0.f); p10 += v * e1.y; p11 += v * e1.z;
            v = fmaxf(acc1[nb][2] + e0.x, 0.f); p12 += v * e0.y; p13 += v * e0.z;
            v = fmaxf(acc1[nb][3] + e1.x, 0.f); p12 += v * e1.y; p13 += v * e1.z;
        }
        #pragma unroll
        for (int s = 1; s <= 2; s <<= 1) {
            p00 += __shfl_xor_sync(0xffffffffu, p00, s);
            p01 += __shfl_xor_sync(0xffffffffu, p01, s);
            p02 += __shfl_xor_sync(0xffffffffu, p02, s);
            p03 += __shfl_xor_sync(0xffffffffu, p03, s);
            p10 += __shfl_xor_sync(0xffffffffu, p10, s);
            p11 += __shfl_xor_sync(0xffffffffu, p11, s);
            p12 += __shfl_xor_sync(0xffffffffu, p12, s);
            p13 += __shfl_xor_sync(0xffffffffu, p13, s);
        }

        const int q = lane >> 2;
        const int m1 = rw * 16 + q;       // local rows m1 and m1+8
        float2* sP0 = (float2*)(sm + SM_PART + (k & 1) * 2048);
        float2* sP1 = sP0 + 128;
        if (ch == 1 && (lane & 3) == 0) {
            sP0[m1]     = make_float2(p00, p01);
            sP0[m1 + 8] = make_float2(p02, p03);
            sP1[m1]     = make_float2(p10, p11);
            sP1[m1 + 8] = make_float2(p12, p13);
        }
        barx(barid);                      // partials visible; pair's MMA done -> A reusable
        if (ch == 0 && (lane & 3) == 0) {
            float* ob = out + (size_t)b * 512;
            #pragma unroll
            for (int tl = 0; tl < 2; tl++) {
                const float2* sp = tl ? sP1 : sP0;
                const float2 q1 = sp[m1], q2 = sp[m1 + 8];
                const float a0 = (tl ? p10 : p00) + q1.x + b3.x;
                const float a1 = (tl ? p11 : p01) + q1.y + b3.y;
                const float a2 = (tl ? p12 : p02) + q2.x + b3.x;
                const float a3 = (tl ? p13 : p03) + q2.y + b3.y;
                const int i1 = tl * 128 + m1, i2 = i1 + 8;
                if (DIR == 0) {
                    if (i1 == 0) *(float2*)ob = make_float2(0.f, 0.f);
                    if (i1 < 255) *(float2*)(ob + (i1 + 1) * 2) = make_float2(a0, a1);
                    if (i2 < 255) *(float2*)(ob + (i2 + 1) * 2) = make_float2(a2, a3);
                } else {
                    if (i1 < 255) {
                        float2* o = (float2*)(ob + i1 * 2);
                        const float2 v = *o; *o = make_float2(v.x + a0, v.y + a1);
                    }
                    if (i2 < 255) {
                        float2* o = (float2*)(ob + i2 * 2);
                        const float2 v = *o; *o = make_float2(v.x + a2, v.y + a3);
                    }
                }
            }
        }
        __syncwarp();
    }
}

// ---------------- init MLP (3->128->128->2, 4096 rows) ----------------
__global__ void __launch_bounds__(128)
init_kernel(const float* __restrict__ x, const float* __restrict__ t,
            const float* __restrict__ W1, const float* __restrict__ b1,
            const float* __restrict__ W2, const float* __restrict__ b2,
            const float* __restrict__ W3, const float* __restrict__ b3,
            float* __restrict__ out, int nrows)
{
    extern __shared__ float ism[];
    float* sW2 = ism;           // 16384
    float* sh  = ism + 16384;   // 128
    float* red = ism + 16512;   // 8
    const int tid = threadIdx.x;
    for (int i = tid; i < 16384; i += 128) sW2[i] = W2[i];
    const float w10 = W1[tid], w11 = W1[128 + tid], w12 = W1[256 + tid];
    const float bb1 = b1[tid], bb2 = b2[tid];
    const float w30 = W3[tid * 2], w31 = W3[tid * 2 + 1];
    __syncthreads();
    for (int r = blockIdx.x; r < nrows; r += gridDim.x) {
        const float2 x0 = *(const float2*)(x + (size_t)r * 514);
        const float tb = t[r];
        sh[tid] = fmaxf(bb1 + x0.x * w10 + x0.y * w11 + tb * w12, 0.f);
        __syncthreads();
        float a = bb2;
        #pragma unroll 8
        for (int k = 0; k < 128; k++) a += sh[k] * sW2[k * 128 + tid];
        a = fmaxf(a, 0.f);
        float p0 = a * w30, p1 = a * w31;
        #pragma unroll
        for (int s = 16; s; s >>= 1) {
            p0 += __shfl_xor_sync(0xffffffffu, p0, s);
            p1 += __shfl_xor_sync(0xffffffffu, p1, s);
        }
        if ((tid & 31) == 0) { red[tid >> 5] = p0; red[4 + (tid >> 5)] = p1; }
        __syncthreads();
        if (tid == 0) {
            const float q0 = red[0] + red[1] + red[2] + red[3] + b3[0];
            const float q1 = red[4] + red[5] + red[6] + red[7] + b3[1];
            float2* o = (float2*)(out + (size_t)r * 512);
            const float2 v = *o; *o = make_float2(v.x + q0, v.y + q1);
        }
        __syncthreads();
    }
}

extern "C" void kernel_launch(void* const* d_in, const int* in_sizes, int n_in,
                              void* d_out, int out_size)
{
    (void)in_sizes; (void)n_in; (void)out_size;
    const float* x = (const float*)d_in[0];
    const float* t = (const float*)d_in[1];
    float* out = (float*)d_out;

    static int grid = 0;
    if (grid == 0) {
        int dev = 0, sms = 148;
        cudaGetDevice(&dev);
        cudaDeviceGetAttribute(&sms, cudaDevAttrMultiProcessorCount, dev);
        grid = sms;
        cudaFuncSetAttribute(fused_kernel<0>, cudaFuncAttributeMaxDynamicSharedMemorySize, SMEM_TOTAL);
        cudaFuncSetAttribute(fused_kernel<1>, cudaFuncAttributeMaxDynamicSharedMemorySize, SMEM_TOTAL);
        cudaFuncSetAttribute(init_kernel, cudaFuncAttributeMaxDynamicSharedMemorySize, 16520 * 4);
    }

    const int npairs = N_B;       // one tile pair (256 rows) per batch

    fused_kernel<0><<<grid, NTHREADS, SMEM_TOTAL>>>(x, t,
        (const float*)d_in[2], (const float*)d_in[3], (const float*)d_in[4],
        (const float*)d_in[5], (const float*)d_in[6], (const float*)d_in[7], out, npairs);
    fused_kernel<1><<<grid, NTHREADS, SMEM_TOTAL>>>(x, t,
        (const float*)d_in[8], (const float*)d_in[9], (const float*)d_in[10],
        (const float*)d_in[11], (const float*)d_in[12], (const float*)d_in[13], out, npairs);
    init_kernel<<<304, 128, 16520 * 4>>>(x, t,
        (const float*)d_in[14], (const float*)d_in[15], (const float*)d_in[16],
        (const float*)d_in[17], (const float*)d_in[18], (const float*)d_in[19], out, N_B);
}